// round 1
// baseline (speedup 1.0000x reference)
#include <cuda_runtime.h>
#include <cuda_bf16.h>

// Problem: QuantizeChannelWise — VQ argmin + gather.
// x: (64,128,32,32) f32 -> queries (8192, 1024), codebook: (1024,1,32,32) -> (1024, 1024).
// score[m,k] = cnorm[k] - 2 * dot(x_m, c_k); argmin_k; out = [selected ; selected].

#define M_Q   8192
#define D_DIM 1024
#define K_CB  1024

#define BM   64
#define BN   64
#define BKD  16
#define NSPLIT 4            // codeword splits (gridDim.y)
#define TILES_PER_SPLIT 4   // (K_CB / NSPLIT) / BN

// __device__ scratch (allocation-free per harness rules)
__device__ float g_cnorm[K_CB];
__device__ float g_pval[M_Q * NSPLIT];
__device__ int   g_pidx[M_Q * NSPLIT];

__global__ void cnorm_kernel(const float* __restrict__ cb) {
    __shared__ float red[256];
    int k = blockIdx.x;
    const float* row = cb + (size_t)k * D_DIM;
    float s = 0.f;
    for (int j = threadIdx.x; j < D_DIM; j += 256) {
        float v = row[j];
        s += v * v;
    }
    red[threadIdx.x] = s;
    __syncthreads();
    for (int off = 128; off > 0; off >>= 1) {
        if (threadIdx.x < off) red[threadIdx.x] += red[threadIdx.x + off];
        __syncthreads();
    }
    if (threadIdx.x == 0) g_cnorm[k] = red[0];
}

// 64x64 fp32 GEMM tile fused with running per-row argmin over this block's
// 256 codewords. Each thread computes a 4x4 micro-tile.
__global__ __launch_bounds__(256) void gemm_argmin_kernel(
    const float* __restrict__ X, const float* __restrict__ CB
) {
    __shared__ __align__(16) float As[BKD][BM + 4];   // row stride 68 floats = 272B (16B aligned)
    __shared__ __align__(16) float Bs[BKD][BN + 4];
    __shared__ float s_cn[BN];
    __shared__ float redv[BM][17];
    __shared__ int   redi[BM][17];

    const int tid = threadIdx.x;
    const int tx = tid & 15;        // 0..15 -> 4 cols each
    const int ty = tid >> 4;        // 0..15 -> 4 rows each
    const int row0 = blockIdx.x * BM;
    const int kc0  = blockIdx.y * (TILES_PER_SPLIT * BN);

    const int lrow = tid >> 2;        // 0..63 (tile row for loads)
    const int lch  = (tid & 3) * 4;   // 0,4,8,12 (d sub-chunk)

    float rv = 3.4e38f;
    int   ri = 0;

    for (int t = 0; t < TILES_PER_SPLIT; ++t) {
        const int col0 = kc0 + t * BN;
        if (tid < BN) s_cn[tid] = g_cnorm[col0 + tid];

        float acc[4][4];
        #pragma unroll
        for (int i = 0; i < 4; i++)
            #pragma unroll
            for (int j = 0; j < 4; j++) acc[i][j] = 0.f;

        for (int d0 = 0; d0 < D_DIM; d0 += BKD) {
            float4 va = *reinterpret_cast<const float4*>(
                X  + (size_t)(row0 + lrow) * D_DIM + d0 + lch);
            float4 vb = *reinterpret_cast<const float4*>(
                CB + (size_t)(col0 + lrow) * D_DIM + d0 + lch);
            __syncthreads();  // previous iter's reads done before overwrite
            As[lch + 0][lrow] = va.x; As[lch + 1][lrow] = va.y;
            As[lch + 2][lrow] = va.z; As[lch + 3][lrow] = va.w;
            Bs[lch + 0][lrow] = vb.x; Bs[lch + 1][lrow] = vb.y;
            Bs[lch + 2][lrow] = vb.z; Bs[lch + 3][lrow] = vb.w;
            __syncthreads();
            #pragma unroll
            for (int dd = 0; dd < BKD; ++dd) {
                float4 a = *reinterpret_cast<const float4*>(&As[dd][ty * 4]);
                float4 b = *reinterpret_cast<const float4*>(&Bs[dd][tx * 4]);
                acc[0][0] += a.x * b.x; acc[0][1] += a.x * b.y;
                acc[0][2] += a.x * b.z; acc[0][3] += a.x * b.w;
                acc[1][0] += a.y * b.x; acc[1][1] += a.y * b.y;
                acc[1][2] += a.y * b.z; acc[1][3] += a.y * b.w;
                acc[2][0] += a.z * b.x; acc[2][1] += a.z * b.y;
                acc[2][2] += a.z * b.z; acc[2][3] += a.z * b.w;
                acc[3][0] += a.w * b.x; acc[3][1] += a.w * b.y;
                acc[3][2] += a.w * b.z; acc[3][3] += a.w * b.w;
            }
        }

        // score = cnorm - 2*dot ; per-thread min over its 4 cols (ascending j
        // + strict < keeps the lowest index on ties, matching jnp.argmin).
        #pragma unroll
        for (int i = 0; i < 4; i++) {
            float bv = 3.4e38f; int bi = 0;
            #pragma unroll
            for (int j = 0; j < 4; j++) {
                float s = s_cn[tx * 4 + j] - 2.0f * acc[i][j];
                if (s < bv) { bv = s; bi = col0 + tx * 4 + j; }
            }
            redv[ty * 4 + i][tx] = bv;
            redi[ty * 4 + i][tx] = bi;
        }
        __syncthreads();
        if (tid < BM) {
            #pragma unroll
            for (int j = 0; j < 16; j++) {   // ascending tx -> ascending col
                float v = redv[tid][j];
                if (v < rv) { rv = v; ri = redi[tid][j]; }
            }
        }
        __syncthreads();
    }

    if (tid < BM) {
        g_pval[(size_t)(row0 + tid) * NSPLIT + blockIdx.y] = rv;
        g_pidx[(size_t)(row0 + tid) * NSPLIT + blockIdx.y] = ri;
    }
}

// One block per query: reduce the NSPLIT partial argmins, then copy the
// selected codeword into both output halves (out, selected).
__global__ void gather_kernel(const float* __restrict__ CB, float* __restrict__ out) {
    __shared__ int sidx;
    const int q = blockIdx.x;
    if (threadIdx.x == 0) {
        float bv = 3.4e38f; int bi = 0;
        #pragma unroll
        for (int p = 0; p < NSPLIT; p++) {   // ascending split -> ascending col
            float v = g_pval[(size_t)q * NSPLIT + p];
            if (v < bv) { bv = v; bi = g_pidx[(size_t)q * NSPLIT + p]; }
        }
        sidx = bi;
    }
    __syncthreads();
    const float4* src = reinterpret_cast<const float4*>(CB + (size_t)sidx * D_DIM);
    float4* o0 = reinterpret_cast<float4*>(out) + (size_t)q * (D_DIM / 4);
    float4* o1 = o0 + (size_t)M_Q * (D_DIM / 4);
    for (int i = threadIdx.x; i < D_DIM / 4; i += blockDim.x) {
        float4 v = src[i];
        o0[i] = v;
        o1[i] = v;
    }
}

extern "C" void kernel_launch(void* const* d_in, const int* in_sizes, int n_in,
                              void* d_out, int out_size) {
    const float* x  = (const float*)d_in[0];   // (64,128,32,32) = (8192,1024)
    const float* cb = (const float*)d_in[1];   // (1024,1,32,32) = (1024,1024)
    float* out = (float*)d_out;                // 2 * 8388608 floats

    cnorm_kernel<<<K_CB, 256>>>(cb);
    dim3 grid(M_Q / BM, NSPLIT);
    gemm_argmin_kernel<<<grid, 256>>>(x, cb);
    gather_kernel<<<M_Q, 128>>>(cb, out);
}

// round 4
// speedup vs baseline: 3.6678x; 3.6678x over previous
#include <cuda_runtime.h>
#include <cuda_bf16.h>
#include <cstdint>

// QuantizeChannelWise: x (8192,1024) f32, codebook (1024,1024) f32.
// score[m,k] = cnorm[k] - 2*dot(x_m,c_k); argmin; out = [selected ; selected].
//
// Path: split-bf16 HMMA (mma.sync m16n8k16, fp32 accum) over Xcat=[Xhi|Xlo]
// vs Chi (B wraps k&1023) -> approx score matrix S; exact fp32 re-rank of
// candidates within EPS of approx min; gather.

#define M_Q   8192
#define K_CB  1024
#define D_DIM 1024
#define KE    2048
#define BM    128
#define BN    128
#define BK    32
#define STAGES 3
#define NITER (KE / BK)        // 64
#define EPS   2.0f

#define A_ROWSTRIDE 40         // bf16 units (80B) -> conflict-free ldmatrix
#define STAGE_BF16 (BM * A_ROWSTRIDE)          // per operand per stage
#define SMEM_BYTES (STAGES * 2 * STAGE_BF16 * 2)  // 61440

// ---------------- device scratch ----------------
__device__ __align__(16) __nv_bfloat16 g_Xcat[(size_t)M_Q * KE];  // 32 MB
__device__ __align__(16) __nv_bfloat16 g_Cbf[(size_t)K_CB * D_DIM]; // 2 MB
__device__ float g_cnorm[K_CB];
__device__ float g_S[(size_t)M_Q * K_CB];                          // 32 MB

// ---------------- small asm helpers ----------------
__device__ __forceinline__ uint32_t smem_u32(const void* p) {
    uint32_t a;
    asm("{ .reg .u64 t; cvta.to.shared.u64 t, %1; cvt.u32.u64 %0, t; }"
        : "=r"(a) : "l"(p));
    return a;
}
__device__ __forceinline__ void cp_async16(uint32_t saddr, const void* gaddr) {
    asm volatile("cp.async.cg.shared.global [%0], [%1], 16;"
                 :: "r"(saddr), "l"(gaddr));
}
__device__ __forceinline__ void cp_commit() {
    asm volatile("cp.async.commit_group;");
}
__device__ __forceinline__ void cp_wait1() {
    asm volatile("cp.async.wait_group 1;");
}
__device__ __forceinline__ void ldmatrix_x4(uint32_t& r0, uint32_t& r1,
                                            uint32_t& r2, uint32_t& r3,
                                            uint32_t addr) {
    asm volatile("ldmatrix.sync.aligned.m8n8.x4.shared.b16 {%0,%1,%2,%3}, [%4];"
                 : "=r"(r0), "=r"(r1), "=r"(r2), "=r"(r3) : "r"(addr));
}
__device__ __forceinline__ void mma_bf16(float& d0, float& d1, float& d2, float& d3,
                                         uint32_t a0, uint32_t a1, uint32_t a2, uint32_t a3,
                                         uint32_t b0, uint32_t b1) {
    asm volatile(
        "mma.sync.aligned.m16n8k16.row.col.f32.bf16.bf16.f32 "
        "{%0,%1,%2,%3}, {%4,%5,%6,%7}, {%8,%9}, {%0,%1,%2,%3};"
        : "+f"(d0), "+f"(d1), "+f"(d2), "+f"(d3)
        : "r"(a0), "r"(a1), "r"(a2), "r"(a3), "r"(b0), "r"(b1));
}

// ---------------- convert kernels ----------------
__global__ __launch_bounds__(256) void convert_x_kernel(const float* __restrict__ X) {
    int q = blockIdx.x, t = threadIdx.x;
    float4 v = reinterpret_cast<const float4*>(X + (size_t)q * D_DIM)[t];
    union { __nv_bfloat16 b[4]; uint2 u; } H, L;
    H.b[0] = __float2bfloat16(v.x); H.b[1] = __float2bfloat16(v.y);
    H.b[2] = __float2bfloat16(v.z); H.b[3] = __float2bfloat16(v.w);
    L.b[0] = __float2bfloat16(v.x - __bfloat162float(H.b[0]));
    L.b[1] = __float2bfloat16(v.y - __bfloat162float(H.b[1]));
    L.b[2] = __float2bfloat16(v.z - __bfloat162float(H.b[2]));
    L.b[3] = __float2bfloat16(v.w - __bfloat162float(H.b[3]));
    __nv_bfloat16* row = g_Xcat + (size_t)q * KE;
    reinterpret_cast<uint2*>(row)[t]         = H.u;   // Xhi: k 0..1023
    reinterpret_cast<uint2*>(row + D_DIM)[t] = L.u;   // Xlo: k 1024..2047
}

__global__ __launch_bounds__(256) void convert_c_kernel(const float* __restrict__ CB) {
    __shared__ float s_red[8];
    int k = blockIdx.x, t = threadIdx.x;
    float4 v = reinterpret_cast<const float4*>(CB + (size_t)k * D_DIM)[t];
    union { __nv_bfloat16 b[4]; uint2 u; } H;
    H.b[0] = __float2bfloat16(v.x); H.b[1] = __float2bfloat16(v.y);
    H.b[2] = __float2bfloat16(v.z); H.b[3] = __float2bfloat16(v.w);
    reinterpret_cast<uint2*>(g_Cbf + (size_t)k * D_DIM)[t] = H.u;
    float ns = v.x * v.x + v.y * v.y + v.z * v.z + v.w * v.w;
    for (int off = 16; off; off >>= 1) ns += __shfl_down_sync(0xffffffffu, ns, off);
    if ((t & 31) == 0) s_red[t >> 5] = ns;
    __syncthreads();
    if (t == 0) {
        float s = 0.f;
        #pragma unroll
        for (int i = 0; i < 8; i++) s += s_red[i];
        g_cnorm[k] = s;
    }
}

// ---------------- HMMA GEMM -> score matrix ----------------
__global__ __launch_bounds__(256, 2) void gemm_kernel() {
    extern __shared__ __align__(128) __nv_bfloat16 smem[];
    // layout: stage s: A at s*2*STAGE_BF16, B at s*2*STAGE_BF16 + STAGE_BF16
    const int tid = threadIdx.x;
    const int wid = tid >> 5, lane = tid & 31;
    const int n0 = blockIdx.x * BN;     // x fastest -> B reuse in-wave
    const int m0 = blockIdx.y * BM;
    const int wm = wid & 3;             // 0..3 -> 32-row slab
    const int wn = wid >> 2;            // 0..1 -> 64-col slab
    const uint32_t sbase = smem_u32(smem);

    // cp.async index precompute: 512 16B-chunks per operand per stage,
    // thread t handles chunks t and t+256. chunk c: row=c>>2, seg=c&3.
    const int r0c = tid >> 2, s0c = (tid & 3) * 8;          // chunk t
    const int r1c = (tid + 256) >> 2, s1c = s0c;            // chunk t+256

    auto issue_stage = [&](int it) {
        const int buf = it % STAGES;
        const int k0 = it * BK;
        __nv_bfloat16* As = smem + buf * 2 * STAGE_BF16;
        __nv_bfloat16* Bs = As + STAGE_BF16;
        const __nv_bfloat16* gA = g_Xcat + (size_t)(m0 + r0c) * KE + k0 + s0c;
        const __nv_bfloat16* gA2 = g_Xcat + (size_t)(m0 + r1c) * KE + k0 + s1c;
        const int kc = k0 & (D_DIM - 1);
        const __nv_bfloat16* gB = g_Cbf + (size_t)(n0 + r0c) * D_DIM + kc + s0c;
        const __nv_bfloat16* gB2 = g_Cbf + (size_t)(n0 + r1c) * D_DIM + kc + s1c;
        cp_async16(smem_u32(As + r0c * A_ROWSTRIDE + s0c), gA);
        cp_async16(smem_u32(As + r1c * A_ROWSTRIDE + s1c), gA2);
        cp_async16(smem_u32(Bs + r0c * A_ROWSTRIDE + s0c), gB);
        cp_async16(smem_u32(Bs + r1c * A_ROWSTRIDE + s1c), gB2);
        cp_commit();
    };

    float d[2][8][4];
    #pragma unroll
    for (int i = 0; i < 2; i++)
        #pragma unroll
        for (int j = 0; j < 8; j++)
            #pragma unroll
            for (int r = 0; r < 4; r++) d[i][j][r] = 0.f;

    issue_stage(0);
    issue_stage(1);
    cp_wait1();
    __syncthreads();

    // ldmatrix lane-address components (element units within a stage tile)
    const int l7 = lane & 7, l3 = (lane >> 3) & 1, l4 = lane >> 4;
    // A: row = wm*32 + mi*16 + l3*8 + l7 ; col = ks*16 + l4*8
    const int a_row = wm * 32 + l3 * 8 + l7;
    const int a_col = l4 * 8;
    // B: for call j: row = wn*64 + 16j + (g>>1)*8 + l7 ; col = ks*16 + (g&1)*8
    const int bg = lane >> 3;
    const int b_row_base = wn * 64 + (bg >> 1) * 8 + l7;
    const int b_col = (bg & 1) * 8;

    for (int it = 0; it < NITER; it++) {
        if (it + 2 < NITER) issue_stage(it + 2);
        const int buf = it % STAGES;
        const uint32_t Asb = sbase + (buf * 2 * STAGE_BF16) * 2;
        const uint32_t Bsb = Asb + STAGE_BF16 * 2;

        #pragma unroll
        for (int ks = 0; ks < 2; ks++) {
            uint32_t a[2][4];
            #pragma unroll
            for (int mi = 0; mi < 2; mi++)
                ldmatrix_x4(a[mi][0], a[mi][1], a[mi][2], a[mi][3],
                    Asb + ((a_row + mi * 16) * A_ROWSTRIDE + ks * 16 + a_col) * 2);
            uint32_t b[8][2];
            #pragma unroll
            for (int j = 0; j < 4; j++) {
                uint32_t r0, r1, r2, r3;
                ldmatrix_x4(r0, r1, r2, r3,
                    Bsb + ((b_row_base + 16 * j) * A_ROWSTRIDE + ks * 16 + b_col) * 2);
                b[2 * j][0] = r0; b[2 * j][1] = r1;
                b[2 * j + 1][0] = r2; b[2 * j + 1][1] = r3;
            }
            #pragma unroll
            for (int mi = 0; mi < 2; mi++)
                #pragma unroll
                for (int nj = 0; nj < 8; nj++)
                    mma_bf16(d[mi][nj][0], d[mi][nj][1], d[mi][nj][2], d[mi][nj][3],
                             a[mi][0], a[mi][1], a[mi][2], a[mi][3],
                             b[nj][0], b[nj][1]);
        }
        cp_wait1();
        __syncthreads();
    }

    // epilogue: score = cnorm - 2*dot -> g_S
    const int gid = lane >> 2, tig = lane & 3;
    #pragma unroll
    for (int mi = 0; mi < 2; mi++) {
        const int mrow = m0 + wm * 32 + mi * 16 + gid;
        #pragma unroll
        for (int nj = 0; nj < 8; nj++) {
            const int ncol = n0 + wn * 64 + nj * 8 + tig * 2;
            const float cn0 = __ldg(&g_cnorm[ncol]);
            const float cn1 = __ldg(&g_cnorm[ncol + 1]);
            float2* p0 = reinterpret_cast<float2*>(g_S + (size_t)mrow * K_CB + ncol);
            float2* p1 = reinterpret_cast<float2*>(g_S + (size_t)(mrow + 8) * K_CB + ncol);
            *p0 = make_float2(cn0 - 2.f * d[mi][nj][0], cn1 - 2.f * d[mi][nj][1]);
            *p1 = make_float2(cn0 - 2.f * d[mi][nj][2], cn1 - 2.f * d[mi][nj][3]);
        }
    }
}

// ---------------- exact re-rank + gather ----------------
__global__ __launch_bounds__(256) void rerank_gather_kernel(
    const float* __restrict__ X, const float* __restrict__ CB, float* __restrict__ out
) {
    __shared__ float s_red[8];
    __shared__ int   s_redi[8];
    __shared__ float s_bv;
    __shared__ int   s_bi, s_cnt;
    __shared__ int   s_cand[64];

    const int q = blockIdx.x, t = threadIdx.x;
    const int warp = t >> 5, lane = t & 31;

    float4 v = reinterpret_cast<const float4*>(g_S + (size_t)q * K_CB)[t];
    float bv = v.x; int bi = 4 * t;
    if (v.y < bv) { bv = v.y; bi = 4 * t + 1; }
    if (v.z < bv) { bv = v.z; bi = 4 * t + 2; }
    if (v.w < bv) { bv = v.w; bi = 4 * t + 3; }
    for (int off = 16; off; off >>= 1) {
        float ov = __shfl_down_sync(0xffffffffu, bv, off);
        int   oi = __shfl_down_sync(0xffffffffu, bi, off);
        if (ov < bv || (ov == bv && oi < bi)) { bv = ov; bi = oi; }
    }
    if (lane == 0) { s_red[warp] = bv; s_redi[warp] = bi; }
    if (t == 0) s_cnt = 0;
    __syncthreads();
    if (t == 0) {
        float rv = s_red[0]; int ri = s_redi[0];
        #pragma unroll
        for (int i = 1; i < 8; i++) {
            float ov = s_red[i]; int oi = s_redi[i];
            if (ov < rv || (ov == rv && oi < ri)) { rv = ov; ri = oi; }
        }
        s_bv = rv; s_bi = ri;
    }
    __syncthreads();

    const float thr = s_bv + EPS;
    if (v.x < thr) { int p = atomicAdd(&s_cnt, 1); if (p < 64) s_cand[p] = 4 * t; }
    if (v.y < thr) { int p = atomicAdd(&s_cnt, 1); if (p < 64) s_cand[p] = 4 * t + 1; }
    if (v.z < thr) { int p = atomicAdd(&s_cnt, 1); if (p < 64) s_cand[p] = 4 * t + 2; }
    if (v.w < thr) { int p = atomicAdd(&s_cnt, 1); if (p < 64) s_cand[p] = 4 * t + 3; }
    __syncthreads();

    int best_i = s_bi;
    const int cnt = (s_cnt < 64) ? s_cnt : 64;
    if (cnt > 1) {  // exact fp32 re-rank
        float4 xv = reinterpret_cast<const float4*>(X + (size_t)q * D_DIM)[t];
        float best_v = 3.4e38f; int best2 = 1 << 30;
        for (int ci = 0; ci < cnt; ci++) {
            const int k = s_cand[ci];
            float4 cv = reinterpret_cast<const float4*>(CB + (size_t)k * D_DIM)[t];
            float part = xv.x * cv.x + xv.y * cv.y + xv.z * cv.z + xv.w * cv.w;
            for (int off = 16; off; off >>= 1)
                part += __shfl_down_sync(0xffffffffu, part, off);
            if (lane == 0) s_red[warp] = part;
            __syncthreads();
            if (t == 0) {
                float dot = 0.f;
                #pragma unroll
                for (int i = 0; i < 8; i++) dot += s_red[i];
                float sc = g_cnorm[k] - 2.0f * dot;
                if (sc < best_v || (sc == best_v && k < best2)) { best_v = sc; best2 = k; }
            }
            __syncthreads();
        }
        if (t == 0) s_bi = best2;
        __syncthreads();
        best_i = s_bi;
    }

    float4 w = reinterpret_cast<const float4*>(CB + (size_t)best_i * D_DIM)[t];
    float4* o0 = reinterpret_cast<float4*>(out) + (size_t)q * (D_DIM / 4);
    float4* o1 = o0 + (size_t)M_Q * (D_DIM / 4);
    o0[t] = w;
    o1[t] = w;
}

// ---------------- host launch ----------------
extern "C" void kernel_launch(void* const* d_in, const int* in_sizes, int n_in,
                              void* d_out, int out_size) {
    const float* x  = (const float*)d_in[0];
    const float* cb = (const float*)d_in[1];
    float* out = (float*)d_out;

    convert_x_kernel<<<M_Q, 256>>>(x);
    convert_c_kernel<<<K_CB, 256>>>(cb);

    static int smem_set = 0;
    if (!smem_set) {
        cudaFuncSetAttribute(gemm_kernel,
                             cudaFuncAttributeMaxDynamicSharedMemorySize, SMEM_BYTES);
        smem_set = 1;
    }
    gemm_kernel<<<dim3(K_CB / BN, M_Q / BM), 256, SMEM_BYTES>>>();

    rerank_gather_kernel<<<M_Q, 256>>>(x, cb, out);
}

// round 5
// speedup vs baseline: 4.1436x; 1.1297x over previous
#include <cuda_runtime.h>
#include <cuda_fp16.h>
#include <cstdint>

// QuantizeChannelWise: x (8192,1024) f32, codebook (1024,1024) f32.
// score[m,k] = cnorm[k] - 2*dot(x_m,c_k); argmin; out = [selected ; selected].
//
// Path: fp16 HMMA (mma.sync m16n8k16, fp32 accum, K=1024) with fused per-tile
// argmin + candidate extraction (no score matrix); finalize kernel picks the
// exact argmin (re-ranking rare near-ties in fp32) and gathers.

#define M_Q   8192
#define K_CB  1024
#define D_DIM 1024
#define BM    128
#define BN    128
#define BK    32
#define STAGES 3
#define NITER (D_DIM / BK)     // 32
#define NTILE (K_CB / BN)      // 8
#define CSLOT 8
#define EPS   1.5f

#define A_ROWSTRIDE 40         // fp16 units (80B) -> conflict-free ldmatrix
#define STAGE_H (BM * A_ROWSTRIDE)
#define SMEM_BYTES (STAGES * 2 * STAGE_H * 2)   // 61440

// ---------------- device scratch ----------------
__device__ __align__(16) __half g_Xh[(size_t)M_Q * D_DIM];    // 16 MB
__device__ __align__(16) __half g_Ch[(size_t)K_CB * D_DIM];   // 2 MB
__device__ float g_cnorm[K_CB];
__device__ float g_cval[(size_t)M_Q * NTILE * CSLOT];         // 2 MB
__device__ int   g_cidx[(size_t)M_Q * NTILE * CSLOT];         // 2 MB
__device__ int   g_ccnt[(size_t)M_Q * NTILE];

// ---------------- helpers ----------------
__device__ __forceinline__ uint32_t smem_u32(const void* p) {
    uint32_t a;
    asm("{ .reg .u64 t; cvta.to.shared.u64 t, %1; cvt.u32.u64 %0, t; }"
        : "=r"(a) : "l"(p));
    return a;
}
__device__ __forceinline__ void cp_async16(uint32_t saddr, const void* gaddr) {
    asm volatile("cp.async.cg.shared.global [%0], [%1], 16;" :: "r"(saddr), "l"(gaddr));
}
__device__ __forceinline__ void cp_commit() { asm volatile("cp.async.commit_group;"); }
__device__ __forceinline__ void cp_wait1()  { asm volatile("cp.async.wait_group 1;"); }
__device__ __forceinline__ void ldmatrix_x4(uint32_t& r0, uint32_t& r1,
                                            uint32_t& r2, uint32_t& r3, uint32_t addr) {
    asm volatile("ldmatrix.sync.aligned.m8n8.x4.shared.b16 {%0,%1,%2,%3}, [%4];"
                 : "=r"(r0), "=r"(r1), "=r"(r2), "=r"(r3) : "r"(addr));
}
__device__ __forceinline__ void mma_f16(float& d0, float& d1, float& d2, float& d3,
                                        uint32_t a0, uint32_t a1, uint32_t a2, uint32_t a3,
                                        uint32_t b0, uint32_t b1) {
    asm volatile(
        "mma.sync.aligned.m16n8k16.row.col.f32.f16.f16.f32 "
        "{%0,%1,%2,%3}, {%4,%5,%6,%7}, {%8,%9}, {%0,%1,%2,%3};"
        : "+f"(d0), "+f"(d1), "+f"(d2), "+f"(d3)
        : "r"(a0), "r"(a1), "r"(a2), "r"(a3), "r"(b0), "r"(b1));
}
// order-preserving float<->uint key
__device__ __forceinline__ uint32_t fkey(float f) {
    uint32_t u = __float_as_uint(f);
    return (u & 0x80000000u) ? ~u : (u | 0x80000000u);
}
__device__ __forceinline__ float kinv(uint32_t k) {
    uint32_t u = (k & 0x80000000u) ? (k & 0x7fffffffu) : ~k;
    return __uint_as_float(u);
}

// ---------------- convert kernels ----------------
__global__ __launch_bounds__(256) void convert_x_kernel(const float* __restrict__ X) {
    int q = blockIdx.x, t = threadIdx.x;
    float4 v = reinterpret_cast<const float4*>(X + (size_t)q * D_DIM)[t];
    union { __half h[4]; uint2 u; } H;
    H.h[0] = __float2half(v.x); H.h[1] = __float2half(v.y);
    H.h[2] = __float2half(v.z); H.h[3] = __float2half(v.w);
    reinterpret_cast<uint2*>(g_Xh + (size_t)q * D_DIM)[t] = H.u;
}

__global__ __launch_bounds__(256) void convert_c_kernel(const float* __restrict__ CB) {
    __shared__ float s_red[8];
    int k = blockIdx.x, t = threadIdx.x;
    float4 v = reinterpret_cast<const float4*>(CB + (size_t)k * D_DIM)[t];
    union { __half h[4]; uint2 u; } H;
    H.h[0] = __float2half(v.x); H.h[1] = __float2half(v.y);
    H.h[2] = __float2half(v.z); H.h[3] = __float2half(v.w);
    reinterpret_cast<uint2*>(g_Ch + (size_t)k * D_DIM)[t] = H.u;
    float ns = v.x * v.x + v.y * v.y + v.z * v.z + v.w * v.w;
    for (int off = 16; off; off >>= 1) ns += __shfl_down_sync(0xffffffffu, ns, off);
    if ((t & 31) == 0) s_red[t >> 5] = ns;
    __syncthreads();
    if (t == 0) {
        float s = 0.f;
        #pragma unroll
        for (int i = 0; i < 8; i++) s += s_red[i];
        g_cnorm[k] = s;
    }
}

// ---------------- HMMA GEMM + fused argmin/candidate epilogue ----------------
__global__ __launch_bounds__(256, 2) void gemm_kernel() {
    extern __shared__ __align__(128) __half smem[];
    const int tid = threadIdx.x;
    const int wid = tid >> 5, lane = tid & 31;
    const int n0 = blockIdx.x * BN;
    const int m0 = blockIdx.y * BM;
    const int wm = wid & 3, wn = wid >> 2;
    const uint32_t sbase = smem_u32(smem);

    const int r0c = tid >> 2, s0c = (tid & 3) * 8;
    const int r1c = (tid + 256) >> 2, s1c = s0c;

    auto issue_stage = [&](int it) {
        const int buf = it % STAGES;
        const int k0 = it * BK;
        __half* As = smem + buf * 2 * STAGE_H;
        __half* Bs = As + STAGE_H;
        cp_async16(smem_u32(As + r0c * A_ROWSTRIDE + s0c),
                   g_Xh + (size_t)(m0 + r0c) * D_DIM + k0 + s0c);
        cp_async16(smem_u32(As + r1c * A_ROWSTRIDE + s1c),
                   g_Xh + (size_t)(m0 + r1c) * D_DIM + k0 + s1c);
        cp_async16(smem_u32(Bs + r0c * A_ROWSTRIDE + s0c),
                   g_Ch + (size_t)(n0 + r0c) * D_DIM + k0 + s0c);
        cp_async16(smem_u32(Bs + r1c * A_ROWSTRIDE + s1c),
                   g_Ch + (size_t)(n0 + r1c) * D_DIM + k0 + s1c);
        cp_commit();
    };

    float d[2][8][4];
    #pragma unroll
    for (int i = 0; i < 2; i++)
        #pragma unroll
        for (int j = 0; j < 8; j++)
            #pragma unroll
            for (int r = 0; r < 4; r++) d[i][j][r] = 0.f;

    issue_stage(0);
    issue_stage(1);
    cp_wait1();
    __syncthreads();

    const int l7 = lane & 7, l3 = (lane >> 3) & 1, l4 = lane >> 4;
    const int a_row = wm * 32 + l3 * 8 + l7;
    const int a_col = l4 * 8;
    const int bg = lane >> 3;
    const int b_row_base = wn * 64 + (bg >> 1) * 8 + l7;
    const int b_col = (bg & 1) * 8;

    for (int it = 0; it < NITER; it++) {
        if (it + 2 < NITER) issue_stage(it + 2);
        const int buf = it % STAGES;
        const uint32_t Asb = sbase + (buf * 2 * STAGE_H) * 2;
        const uint32_t Bsb = Asb + STAGE_H * 2;

        #pragma unroll
        for (int ks = 0; ks < 2; ks++) {
            uint32_t a[2][4];
            #pragma unroll
            for (int mi = 0; mi < 2; mi++)
                ldmatrix_x4(a[mi][0], a[mi][1], a[mi][2], a[mi][3],
                    Asb + ((a_row + mi * 16) * A_ROWSTRIDE + ks * 16 + a_col) * 2);
            uint32_t b[8][2];
            #pragma unroll
            for (int j = 0; j < 4; j++) {
                uint32_t r0, r1, r2, r3;
                ldmatrix_x4(r0, r1, r2, r3,
                    Bsb + ((b_row_base + 16 * j) * A_ROWSTRIDE + ks * 16 + b_col) * 2);
                b[2 * j][0] = r0; b[2 * j][1] = r1;
                b[2 * j + 1][0] = r2; b[2 * j + 1][1] = r3;
            }
            #pragma unroll
            for (int mi = 0; mi < 2; mi++)
                #pragma unroll
                for (int nj = 0; nj < 8; nj++)
                    mma_f16(d[mi][nj][0], d[mi][nj][1], d[mi][nj][2], d[mi][nj][3],
                            a[mi][0], a[mi][1], a[mi][2], a[mi][3],
                            b[nj][0], b[nj][1]);
        }
        cp_wait1();
        __syncthreads();
    }

    // ---- fused epilogue: per-row tile-min + candidate extraction ----
    __syncthreads();   // mainloop smem dead; re-purpose it
    uint32_t* s_min = reinterpret_cast<uint32_t*>(smem);        // [128]
    int*      s_cnt = reinterpret_cast<int*>(s_min + BM);       // [128]
    float*    s_cv  = reinterpret_cast<float*>(s_cnt + BM);     // [128*CSLOT]
    int*      s_ci  = reinterpret_cast<int*>(s_cv + BM * CSLOT);// [128*CSLOT]

    for (int i = tid; i < BM; i += 256) { s_min[i] = 0xFFFFFFFFu; s_cnt[i] = 0; }
    __syncthreads();

    const int gid = lane >> 2, tig = lane & 3;
    float cn[8][2];
    #pragma unroll
    for (int nj = 0; nj < 8; nj++) {
        const int ncol = n0 + wn * 64 + nj * 8 + tig * 2;
        cn[nj][0] = __ldg(&g_cnorm[ncol]);
        cn[nj][1] = __ldg(&g_cnorm[ncol + 1]);
    }

    #pragma unroll
    for (int mi = 0; mi < 2; mi++)
        #pragma unroll
        for (int h = 0; h < 2; h++) {
            const int rl = wm * 32 + mi * 16 + gid + h * 8;
            float mn = 3.4e38f;
            #pragma unroll
            for (int nj = 0; nj < 8; nj++)
                #pragma unroll
                for (int e = 0; e < 2; e++) {
                    float sc = cn[nj][e] - 2.0f * d[mi][nj][h * 2 + e];
                    if (sc < mn) mn = sc;
                }
            atomicMin(&s_min[rl], fkey(mn));
        }
    __syncthreads();

    #pragma unroll
    for (int mi = 0; mi < 2; mi++)
        #pragma unroll
        for (int h = 0; h < 2; h++) {
            const int rl = wm * 32 + mi * 16 + gid + h * 8;
            const float thr = kinv(s_min[rl]) + EPS;
            #pragma unroll
            for (int nj = 0; nj < 8; nj++)
                #pragma unroll
                for (int e = 0; e < 2; e++) {
                    float sc = cn[nj][e] - 2.0f * d[mi][nj][h * 2 + e];
                    if (sc < thr) {
                        int p = atomicAdd(&s_cnt[rl], 1);
                        if (p < CSLOT) {
                            s_cv[rl * CSLOT + p] = sc;
                            s_ci[rl * CSLOT + p] = n0 + wn * 64 + nj * 8 + tig * 2 + e;
                        }
                    }
                }
        }
    __syncthreads();

    if (tid < BM) {
        const int c = s_cnt[tid];
        const size_t base = ((size_t)(m0 + tid) * NTILE + blockIdx.x) * CSLOT;
        g_ccnt[(size_t)(m0 + tid) * NTILE + blockIdx.x] = c;
        const int cc = (c < CSLOT) ? c : CSLOT;
        for (int s = 0; s < cc; s++) {
            g_cval[base + s] = s_cv[tid * CSLOT + s];
            g_cidx[base + s] = s_ci[tid * CSLOT + s];
        }
    }
}

// ---------------- finalize: pick argmin (exact where needed) + gather ----------------
__global__ __launch_bounds__(256) void finalize_kernel(
    const float* __restrict__ X, const float* __restrict__ CB, float* __restrict__ out
) {
    __shared__ float s_v[NTILE * CSLOT];
    __shared__ int   s_i[NTILE * CSLOT];
    __shared__ float s_fv[NTILE * CSLOT];
    __shared__ int   s_fi[NTILE * CSLOT];
    __shared__ int   s_nf, s_over, s_best;
    __shared__ float s_red[8];
    __shared__ int   s_redi[8];

    const int q = blockIdx.x, t = threadIdx.x;
    const int warp = t >> 5, lane = t & 31;

    if (t == 0) { s_over = 0; }
    __syncthreads();
    if (t < NTILE * CSLOT) {
        const int tile = t >> 3, slot = t & 7;
        const int c = g_ccnt[(size_t)q * NTILE + tile];
        if (slot == 0 && c > CSLOT) atomicOr(&s_over, 1);
        const bool va = slot < ((c < CSLOT) ? c : CSLOT);
        s_v[t] = va ? g_cval[((size_t)q * NTILE + tile) * CSLOT + slot] : 3.4e38f;
        s_i[t] = va ? g_cidx[((size_t)q * NTILE + tile) * CSLOT + slot] : 0x7fffffff;
    }
    __syncthreads();
    if (t == 0) {
        float g = 3.4e38f;
        for (int i = 0; i < NTILE * CSLOT; i++) if (s_v[i] < g) g = s_v[i];
        const float thr = g + EPS;
        int nf = 0;
        for (int i = 0; i < NTILE * CSLOT; i++)
            if (s_v[i] < thr) { s_fv[nf] = s_v[i]; s_fi[nf] = s_i[i]; nf++; }
        s_nf = nf;
        if (nf == 1) s_best = s_fi[0];
    }
    __syncthreads();

    if (s_over) {
        // exact full scan fallback (astronomically rare; correctness guard)
        float bv = 3.4e38f; int bi = 0x7fffffff;
        const float4* xv4 = reinterpret_cast<const float4*>(X + (size_t)q * D_DIM);
        for (int k = warp; k < K_CB; k += 8) {
            const float4* cv4 = reinterpret_cast<const float4*>(CB + (size_t)k * D_DIM);
            float p = 0.f;
            for (int j = lane; j < D_DIM / 4; j += 32) {
                float4 a = xv4[j], b = cv4[j];
                p += a.x * b.x + a.y * b.y + a.z * b.z + a.w * b.w;
            }
            for (int off = 16; off; off >>= 1) p += __shfl_down_sync(0xffffffffu, p, off);
            if (lane == 0) {
                float sc = g_cnorm[k] - 2.0f * p;
                if (sc < bv || (sc == bv && k < bi)) { bv = sc; bi = k; }
            }
        }
        if (lane == 0) { s_red[warp] = bv; s_redi[warp] = bi; }
        __syncthreads();
        if (t == 0) {
            float rv = s_red[0]; int ri = s_redi[0];
            for (int i = 1; i < 8; i++)
                if (s_red[i] < rv || (s_red[i] == rv && s_redi[i] < ri))
                    { rv = s_red[i]; ri = s_redi[i]; }
            s_best = ri;
        }
        __syncthreads();
    } else if (s_nf > 1) {
        // exact fp32 re-rank of the filtered candidates
        const int nf = s_nf;
        const float4 xv = reinterpret_cast<const float4*>(X + (size_t)q * D_DIM)[t];
        float best_v = 3.4e38f; int best2 = 0x7fffffff;
        for (int ci = 0; ci < nf; ci++) {
            const int k = s_fi[ci];
            float4 cv = reinterpret_cast<const float4*>(CB + (size_t)k * D_DIM)[t];
            float part = xv.x * cv.x + xv.y * cv.y + xv.z * cv.z + xv.w * cv.w;
            for (int off = 16; off; off >>= 1)
                part += __shfl_down_sync(0xffffffffu, part, off);
            if (lane == 0) s_red[warp] = part;
            __syncthreads();
            if (t == 0) {
                float dot = 0.f;
                #pragma unroll
                for (int i = 0; i < 8; i++) dot += s_red[i];
                float sc = g_cnorm[k] - 2.0f * dot;
                if (sc < best_v || (sc == best_v && k < best2)) { best_v = sc; best2 = k; }
            }
            __syncthreads();
        }
        if (t == 0) s_best = best2;
        __syncthreads();
    }

    const int best_i = s_best;
    float4 w = reinterpret_cast<const float4*>(CB + (size_t)best_i * D_DIM)[t];
    float4* o0 = reinterpret_cast<float4*>(out) + (size_t)q * (D_DIM / 4);
    float4* o1 = o0 + (size_t)M_Q * (D_DIM / 4);
    o0[t] = w;
    o1[t] = w;
}

// ---------------- host launch ----------------
extern "C" void kernel_launch(void* const* d_in, const int* in_sizes, int n_in,
                              void* d_out, int out_size) {
    const float* x  = (const float*)d_in[0];
    const float* cb = (const float*)d_in[1];
    float* out = (float*)d_out;

    convert_x_kernel<<<M_Q, 256>>>(x);
    convert_c_kernel<<<K_CB, 256>>>(cb);

    static int smem_set = 0;
    if (!smem_set) {
        cudaFuncSetAttribute(gemm_kernel,
                             cudaFuncAttributeMaxDynamicSharedMemorySize, SMEM_BYTES);
        smem_set = 1;
    }
    gemm_kernel<<<dim3(K_CB / BN, M_Q / BM), 256, SMEM_BYTES>>>();

    finalize_kernel<<<M_Q, 256>>>(x, cb, out);
}

// round 6
// speedup vs baseline: 5.6039x; 1.3524x over previous
#include <cuda_runtime.h>
#include <cuda_fp16.h>
#include <cstdint>

// QuantizeChannelWise: x (8192,1024) f32, codebook (1024,1024) f32.
// score[m,k] = cnorm[k] - 2*dot(x_m,c_k); argmin; out = [selected ; selected].
//
// fp16 HMMA GEMM (fp32 accum) with fused per-tile argmin + candidate extraction;
// warp-parallel select (exact fp32 re-rank of near-ties); streaming gather.

#define M_Q   8192
#define K_CB  1024
#define D_DIM 1024
#define BM    128
#define BN    128
#define BK    32
#define STAGES 3
#define NITER (D_DIM / BK)     // 32
#define NTILE (K_CB / BN)      // 8
#define CSLOT 8
#define EPS   1.5f

#define A_ROWSTRIDE 40
#define STAGE_H (BM * A_ROWSTRIDE)
#define SMEM_BYTES (STAGES * 2 * STAGE_H * 2)   // 61440

// ---------------- device scratch ----------------
__device__ __align__(16) __half g_Xh[(size_t)M_Q * D_DIM];    // 16 MB
__device__ __align__(16) __half g_Ch[(size_t)K_CB * D_DIM];   // 2 MB
__device__ float g_cnorm[K_CB];
__device__ float g_cval[(size_t)M_Q * NTILE * CSLOT];
__device__ int   g_cidx[(size_t)M_Q * NTILE * CSLOT];
__device__ int   g_ccnt[(size_t)M_Q * NTILE];
__device__ int   g_best[M_Q];

// ---------------- helpers ----------------
__device__ __forceinline__ uint32_t smem_u32(const void* p) {
    uint32_t a;
    asm("{ .reg .u64 t; cvta.to.shared.u64 t, %1; cvt.u32.u64 %0, t; }"
        : "=r"(a) : "l"(p));
    return a;
}
__device__ __forceinline__ void cp_async16(uint32_t saddr, const void* gaddr) {
    asm volatile("cp.async.cg.shared.global [%0], [%1], 16;" :: "r"(saddr), "l"(gaddr));
}
__device__ __forceinline__ void cp_commit() { asm volatile("cp.async.commit_group;"); }
__device__ __forceinline__ void cp_wait1()  { asm volatile("cp.async.wait_group 1;"); }
__device__ __forceinline__ void ldmatrix_x4(uint32_t& r0, uint32_t& r1,
                                            uint32_t& r2, uint32_t& r3, uint32_t addr) {
    asm volatile("ldmatrix.sync.aligned.m8n8.x4.shared.b16 {%0,%1,%2,%3}, [%4];"
                 : "=r"(r0), "=r"(r1), "=r"(r2), "=r"(r3) : "r"(addr));
}
__device__ __forceinline__ void mma_f16(float& d0, float& d1, float& d2, float& d3,
                                        uint32_t a0, uint32_t a1, uint32_t a2, uint32_t a3,
                                        uint32_t b0, uint32_t b1) {
    asm volatile(
        "mma.sync.aligned.m16n8k16.row.col.f32.f16.f16.f32 "
        "{%0,%1,%2,%3}, {%4,%5,%6,%7}, {%8,%9}, {%0,%1,%2,%3};"
        : "+f"(d0), "+f"(d1), "+f"(d2), "+f"(d3)
        : "r"(a0), "r"(a1), "r"(a2), "r"(a3), "r"(b0), "r"(b1));
}
__device__ __forceinline__ uint32_t fkey(float f) {
    uint32_t u = __float_as_uint(f);
    return (u & 0x80000000u) ? ~u : (u | 0x80000000u);
}
__device__ __forceinline__ float kinv(uint32_t k) {
    uint32_t u = (k & 0x80000000u) ? (k & 0x7fffffffu) : ~k;
    return __uint_as_float(u);
}

// ---------------- convert kernels ----------------
__global__ __launch_bounds__(256) void convert_x_kernel(const float* __restrict__ X) {
    int q = blockIdx.x, t = threadIdx.x;
    float4 v = reinterpret_cast<const float4*>(X + (size_t)q * D_DIM)[t];
    union { __half h[4]; uint2 u; } H;
    H.h[0] = __float2half(v.x); H.h[1] = __float2half(v.y);
    H.h[2] = __float2half(v.z); H.h[3] = __float2half(v.w);
    reinterpret_cast<uint2*>(g_Xh + (size_t)q * D_DIM)[t] = H.u;
}

__global__ __launch_bounds__(256) void convert_c_kernel(const float* __restrict__ CB) {
    __shared__ float s_red[8];
    int k = blockIdx.x, t = threadIdx.x;
    float4 v = reinterpret_cast<const float4*>(CB + (size_t)k * D_DIM)[t];
    union { __half h[4]; uint2 u; } H;
    H.h[0] = __float2half(v.x); H.h[1] = __float2half(v.y);
    H.h[2] = __float2half(v.z); H.h[3] = __float2half(v.w);
    reinterpret_cast<uint2*>(g_Ch + (size_t)k * D_DIM)[t] = H.u;
    float ns = v.x * v.x + v.y * v.y + v.z * v.z + v.w * v.w;
    for (int off = 16; off; off >>= 1) ns += __shfl_down_sync(0xffffffffu, ns, off);
    if ((t & 31) == 0) s_red[t >> 5] = ns;
    __syncthreads();
    if (t == 0) {
        float s = 0.f;
        #pragma unroll
        for (int i = 0; i < 8; i++) s += s_red[i];
        g_cnorm[k] = s;
    }
}

// ---------------- HMMA GEMM + fused argmin/candidate epilogue ----------------
__global__ __launch_bounds__(256, 2) void gemm_kernel() {
    extern __shared__ __align__(128) __half smem[];
    const int tid = threadIdx.x;
    const int wid = tid >> 5, lane = tid & 31;
    const int n0 = blockIdx.x * BN;
    const int m0 = blockIdx.y * BM;
    const int wm = wid & 3, wn = wid >> 2;
    const uint32_t sbase = smem_u32(smem);

    const int r0c = tid >> 2, s0c = (tid & 3) * 8;
    const int r1c = (tid + 256) >> 2, s1c = s0c;

    auto issue_stage = [&](int it) {
        const int buf = it % STAGES;
        const int k0 = it * BK;
        __half* As = smem + buf * 2 * STAGE_H;
        __half* Bs = As + STAGE_H;
        cp_async16(smem_u32(As + r0c * A_ROWSTRIDE + s0c),
                   g_Xh + (size_t)(m0 + r0c) * D_DIM + k0 + s0c);
        cp_async16(smem_u32(As + r1c * A_ROWSTRIDE + s1c),
                   g_Xh + (size_t)(m0 + r1c) * D_DIM + k0 + s1c);
        cp_async16(smem_u32(Bs + r0c * A_ROWSTRIDE + s0c),
                   g_Ch + (size_t)(n0 + r0c) * D_DIM + k0 + s0c);
        cp_async16(smem_u32(Bs + r1c * A_ROWSTRIDE + s1c),
                   g_Ch + (size_t)(n0 + r1c) * D_DIM + k0 + s1c);
        cp_commit();
    };

    float d[2][8][4];
    #pragma unroll
    for (int i = 0; i < 2; i++)
        #pragma unroll
        for (int j = 0; j < 8; j++)
            #pragma unroll
            for (int r = 0; r < 4; r++) d[i][j][r] = 0.f;

    issue_stage(0);
    issue_stage(1);
    cp_wait1();
    __syncthreads();

    const int l7 = lane & 7, l3 = (lane >> 3) & 1, l4 = lane >> 4;
    const int a_row = wm * 32 + l3 * 8 + l7;
    const int a_col = l4 * 8;
    const int bg = lane >> 3;
    const int b_row_base = wn * 64 + (bg >> 1) * 8 + l7;
    const int b_col = (bg & 1) * 8;

    for (int it = 0; it < NITER; it++) {
        if (it + 2 < NITER) issue_stage(it + 2);
        const int buf = it % STAGES;
        const uint32_t Asb = sbase + (buf * 2 * STAGE_H) * 2;
        const uint32_t Bsb = Asb + STAGE_H * 2;

        #pragma unroll
        for (int ks = 0; ks < 2; ks++) {
            uint32_t a[2][4];
            #pragma unroll
            for (int mi = 0; mi < 2; mi++)
                ldmatrix_x4(a[mi][0], a[mi][1], a[mi][2], a[mi][3],
                    Asb + ((a_row + mi * 16) * A_ROWSTRIDE + ks * 16 + a_col) * 2);
            uint32_t b[8][2];
            #pragma unroll
            for (int j = 0; j < 4; j++) {
                uint32_t r0, r1, r2, r3;
                ldmatrix_x4(r0, r1, r2, r3,
                    Bsb + ((b_row_base + 16 * j) * A_ROWSTRIDE + ks * 16 + b_col) * 2);
                b[2 * j][0] = r0; b[2 * j][1] = r1;
                b[2 * j + 1][0] = r2; b[2 * j + 1][1] = r3;
            }
            #pragma unroll
            for (int mi = 0; mi < 2; mi++)
                #pragma unroll
                for (int nj = 0; nj < 8; nj++)
                    mma_f16(d[mi][nj][0], d[mi][nj][1], d[mi][nj][2], d[mi][nj][3],
                            a[mi][0], a[mi][1], a[mi][2], a[mi][3],
                            b[nj][0], b[nj][1]);
        }
        cp_wait1();
        __syncthreads();
    }

    // ---- fused epilogue: per-row tile-min + candidate extraction ----
    __syncthreads();
    uint32_t* s_min = reinterpret_cast<uint32_t*>(smem);
    int*      s_cnt = reinterpret_cast<int*>(s_min + BM);
    float*    s_cv  = reinterpret_cast<float*>(s_cnt + BM);
    int*      s_ci  = reinterpret_cast<int*>(s_cv + BM * CSLOT);

    for (int i = tid; i < BM; i += 256) { s_min[i] = 0xFFFFFFFFu; s_cnt[i] = 0; }
    __syncthreads();

    const int gid = lane >> 2, tig = lane & 3;
    float cn[8][2];
    #pragma unroll
    for (int nj = 0; nj < 8; nj++) {
        const int ncol = n0 + wn * 64 + nj * 8 + tig * 2;
        cn[nj][0] = __ldg(&g_cnorm[ncol]);
        cn[nj][1] = __ldg(&g_cnorm[ncol + 1]);
    }

    #pragma unroll
    for (int mi = 0; mi < 2; mi++)
        #pragma unroll
        for (int h = 0; h < 2; h++) {
            const int rl = wm * 32 + mi * 16 + gid + h * 8;
            float mn = 3.4e38f;
            #pragma unroll
            for (int nj = 0; nj < 8; nj++)
                #pragma unroll
                for (int e = 0; e < 2; e++) {
                    float sc = cn[nj][e] - 2.0f * d[mi][nj][h * 2 + e];
                    if (sc < mn) mn = sc;
                }
            atomicMin(&s_min[rl], fkey(mn));
        }
    __syncthreads();

    #pragma unroll
    for (int mi = 0; mi < 2; mi++)
        #pragma unroll
        for (int h = 0; h < 2; h++) {
            const int rl = wm * 32 + mi * 16 + gid + h * 8;
            const float thr = kinv(s_min[rl]) + EPS;
            #pragma unroll
            for (int nj = 0; nj < 8; nj++)
                #pragma unroll
                for (int e = 0; e < 2; e++) {
                    float sc = cn[nj][e] - 2.0f * d[mi][nj][h * 2 + e];
                    if (sc < thr) {
                        int p = atomicAdd(&s_cnt[rl], 1);
                        if (p < CSLOT) {
                            s_cv[rl * CSLOT + p] = sc;
                            s_ci[rl * CSLOT + p] = n0 + wn * 64 + nj * 8 + tig * 2 + e;
                        }
                    }
                }
        }
    __syncthreads();

    if (tid < BM) {
        const int c = s_cnt[tid];
        const size_t base = ((size_t)(m0 + tid) * NTILE + blockIdx.x) * CSLOT;
        g_ccnt[(size_t)(m0 + tid) * NTILE + blockIdx.x] = c;
        const int cc = (c < CSLOT) ? c : CSLOT;
        for (int s = 0; s < cc; s++) {
            g_cval[base + s] = s_cv[tid * CSLOT + s];
            g_cidx[base + s] = s_ci[tid * CSLOT + s];
        }
    }
}

// ---------------- select: one warp per query -> g_best[q] ----------------
__global__ __launch_bounds__(256) void select_kernel(
    const float* __restrict__ X, const float* __restrict__ CB
) {
    __shared__ int s_cand[8][64];
    const int warp = threadIdx.x >> 5, lane = threadIdx.x & 31;
    const int q = blockIdx.x * 8 + warp;

    // two slots per lane: s0 = lane, s1 = lane + 32 (of NTILE*CSLOT = 64)
    const int t0 = lane >> 3, sl0 = lane & 7;
    const int t1 = (lane + 32) >> 3, sl1 = lane & 7;
    const int c0 = g_ccnt[(size_t)q * NTILE + t0];
    const int c1 = g_ccnt[(size_t)q * NTILE + t1];
    const bool over = __any_sync(0xffffffffu, (c0 > CSLOT) || (c1 > CSLOT));

    const size_t b0 = ((size_t)q * NTILE + t0) * CSLOT + sl0;
    const size_t b1 = ((size_t)q * NTILE + t1) * CSLOT + sl1;
    float v0 = (sl0 < c0) ? g_cval[b0] : 3.4e38f;
    float v1 = (sl1 < c1) ? g_cval[b1] : 3.4e38f;
    int   i0 = (sl0 < c0) ? g_cidx[b0] : 0x7fffffff;
    int   i1 = (sl1 < c1) ? g_cidx[b1] : 0x7fffffff;

    float bv = v0; int bi = i0;
    if (v1 < bv || (v1 == bv && i1 < bi)) { bv = v1; bi = i1; }
    #pragma unroll
    for (int off = 16; off; off >>= 1) {
        float ov = __shfl_down_sync(0xffffffffu, bv, off);
        int   oi = __shfl_down_sync(0xffffffffu, bi, off);
        if (ov < bv || (ov == bv && oi < bi)) { bv = ov; bi = oi; }
    }
    bv = __shfl_sync(0xffffffffu, bv, 0);
    bi = __shfl_sync(0xffffffffu, bi, 0);

    const float thr = bv + EPS;
    const uint32_t m0b = __ballot_sync(0xffffffffu, v0 < thr);
    const uint32_t m1b = __ballot_sync(0xffffffffu, v1 < thr);
    const int n0c = __popc(m0b);
    const int n = n0c + __popc(m1b);

    if (!over && n <= 1) {          // fast path: unique candidate
        if (lane == 0) g_best[q] = bi;
        return;
    }

    float best_v = 3.4e38f; int best_i = 0x7fffffff;
    int nc = n;
    if (over) {
        nc = 0;                     // force full scan below
    } else {
        const uint32_t lt = (1u << lane) - 1u;
        if (v0 < thr) s_cand[warp][__popc(m0b & lt)] = i0;
        if (v1 < thr) s_cand[warp][n0c + __popc(m1b & lt)] = i1;
        __syncwarp();
    }

    if (nc > 0) {                   // exact fp32 re-rank of candidates
        const float4* xr = reinterpret_cast<const float4*>(X + (size_t)q * D_DIM);
        for (int ci = 0; ci < nc; ci++) {
            const int k = s_cand[warp][ci];
            const float4* cr = reinterpret_cast<const float4*>(CB + (size_t)k * D_DIM);
            float p = 0.f;
            #pragma unroll
            for (int j = 0; j < 8; j++) {
                float4 a = xr[lane + 32 * j], c = cr[lane + 32 * j];
                p += a.x * c.x + a.y * c.y + a.z * c.z + a.w * c.w;
            }
            #pragma unroll
            for (int off = 16; off; off >>= 1)
                p += __shfl_down_sync(0xffffffffu, p, off);
            if (lane == 0) {
                float sc = g_cnorm[k] - 2.0f * p;
                if (sc < best_v || (sc == best_v && k < best_i)) { best_v = sc; best_i = k; }
            }
        }
    } else {                        // overflow guard: exact full scan
        const float4* xr = reinterpret_cast<const float4*>(X + (size_t)q * D_DIM);
        for (int k = 0; k < K_CB; k++) {
            const float4* cr = reinterpret_cast<const float4*>(CB + (size_t)k * D_DIM);
            float p = 0.f;
            #pragma unroll
            for (int j = 0; j < 8; j++) {
                float4 a = xr[lane + 32 * j], c = cr[lane + 32 * j];
                p += a.x * c.x + a.y * c.y + a.z * c.z + a.w * c.w;
            }
            #pragma unroll
            for (int off = 16; off; off >>= 1)
                p += __shfl_down_sync(0xffffffffu, p, off);
            if (lane == 0) {
                float sc = g_cnorm[k] - 2.0f * p;
                if (sc < best_v || (sc == best_v && k < best_i)) { best_v = sc; best_i = k; }
            }
        }
    }
    if (lane == 0) g_best[q] = best_i;
}

// ---------------- gather: streaming copy of selected codeword ----------------
__global__ __launch_bounds__(256) void gather_kernel(
    const float* __restrict__ CB, float* __restrict__ out
) {
    const int q = blockIdx.x, t = threadIdx.x;
    const int b = g_best[q];                       // uniform load
    const float4 w = reinterpret_cast<const float4*>(CB + (size_t)b * D_DIM)[t];
    float4* o0 = reinterpret_cast<float4*>(out) + (size_t)q * (D_DIM / 4);
    o0[t] = w;
    o0[t + (size_t)M_Q * (D_DIM / 4)] = w;
}

// ---------------- host launch ----------------
extern "C" void kernel_launch(void* const* d_in, const int* in_sizes, int n_in,
                              void* d_out, int out_size) {
    const float* x  = (const float*)d_in[0];
    const float* cb = (const float*)d_in[1];
    float* out = (float*)d_out;

    convert_x_kernel<<<M_Q, 256>>>(x);
    convert_c_kernel<<<K_CB, 256>>>(cb);

    static int smem_set = 0;
    if (!smem_set) {
        cudaFuncSetAttribute(gemm_kernel,
                             cudaFuncAttributeMaxDynamicSharedMemorySize, SMEM_BYTES);
        smem_set = 1;
    }
    gemm_kernel<<<dim3(K_CB / BN, M_Q / BM), 256, SMEM_BYTES>>>();

    select_kernel<<<M_Q / 8, 256>>>(x, cb);
    gather_kernel<<<M_Q, 256>>>(cb, out);
}